// round 8
// baseline (speedup 1.0000x reference)
#include <cuda_runtime.h>

// LIF neuron recurrence, fully parallel across B*N neurons, serial over T.
//   out[t]  = (mem > 1.0f) ? 1 : 0
//   mem     = (0.5f*mem + syn) * (1 - out[t])
//   syn     = in[t]
// inputs: [T=100, B=256, N=2048] fp32 contiguous; output same shape.
//
// R8 (final): R6 winning structure (float4, 512x256, software-pipelined
// prefetch; 61.06us kernel, DRAM 76.3%) with pipeline depth 2.
// Roofline conclusion after 7 measured configs: ~6.0TB/s (75-76% of 8TB/s
// spec) is the achievable mixed R/W DRAM ceiling — invariant across vector
// width (64/128/256-bit), occupancy (13-54 warps/SM), cache hints, burst
// batching, and prefetch depth. Traffic is fixed at 419.4MB, so this kernel
// is memory-roofline-bound; remaining gap to spec is DRAM-controller
// overhead (turnaround/refresh), not addressable from the SM.

constexpr int T_STEPS = 100;

__global__ void __launch_bounds__(256) lif_kernel(
    const float4* __restrict__ in,
    float4* __restrict__ out,
    int n4)
{
    int i = blockIdx.x * blockDim.x + threadIdx.x;
    if (i >= n4) return;

    float4 mem = make_float4(0.f, 0.f, 0.f, 0.f);
    float4 syn = make_float4(0.f, 0.f, 0.f, 0.f);

    size_t idx = (size_t)i;
    const size_t stride = (size_t)n4;

    // Prologue: 2 loads in flight before the loop body.
    float4 x0 = in[idx];
    float4 x1 = in[idx + stride];

    #pragma unroll 5
    for (int t = 0; t < T_STEPS; ++t) {
        // Prefetch t+2 before this iteration's store (3 reads in flight).
        float4 x2;
        if (t + 2 < T_STEPS)
            x2 = in[idx + 2 * stride];

        float4 o;
        o.x = (mem.x > 1.0f) ? 1.0f : 0.0f;
        o.y = (mem.y > 1.0f) ? 1.0f : 0.0f;
        o.z = (mem.z > 1.0f) ? 1.0f : 0.0f;
        o.w = (mem.w > 1.0f) ? 1.0f : 0.0f;

        out[idx] = o;

        mem.x = (0.5f * mem.x + syn.x) * (1.0f - o.x);
        mem.y = (0.5f * mem.y + syn.y) * (1.0f - o.y);
        mem.z = (0.5f * mem.z + syn.z) * (1.0f - o.z);
        mem.w = (0.5f * mem.w + syn.w) * (1.0f - o.w);

        syn = x0;
        x0 = x1;
        x1 = x2;
        idx += stride;
    }
}

extern "C" void kernel_launch(void* const* d_in, const int* in_sizes, int n_in,
                              void* d_out, int out_size)
{
    const float* in = (const float*)d_in[0];
    float* out = (float*)d_out;

    const int BN = in_sizes[0] / T_STEPS;  // 524288
    const int n4 = BN / 4;                 // 131072 float4 lanes

    const int threads = 256;
    const int blocks = (n4 + threads - 1) / threads;  // 512

    lif_kernel<<<blocks, threads>>>(
        (const float4*)in, (float4*)out, n4);
}

// round 9
// speedup vs baseline: 1.0719x; 1.0719x over previous
#include <cuda_runtime.h>

// LIF neuron recurrence, fully parallel across B*N neurons, serial over T.
//   out[t]  = (mem > 1.0f) ? 1 : 0
//   mem     = (0.5f*mem + syn) * (1 - out[t])
//   syn     = in[t]
// inputs: [T=100, B=256, N=2048] fp32 contiguous; output same shape.
//
// FINAL (= R6, best of 9 measured configs: 61.06us kernel / 76.3% DRAM /
// 6041 GB/s). float4 per thread, 512 blocks x 256 threads (27 warps/SM),
// software-pipelined prefetch depth 1: load x(t+1) before storing o(t), so
// each warp keeps 2 reads in flight across the store and the LDG->syn
// dependency is decoupled by one iteration.
//
// Roofline conclusion from the session: ~6.0TB/s (75-76% of 8TB/s spec) is
// the achievable mixed R/W DRAM ceiling here — invariant across vector width
// (64/128/256-bit), occupancy (13-54 warps/SM), cache hints (__ldcs/__stcs
// regressed), read/write burst batching (neutral), and prefetch depth 2
// (regressed: predicated in-body loads + 3-deep register rotation defeated
// ptxas renaming). Traffic is fixed at 419.4MB -> this kernel is at the
// memory roofline; the gap to spec is DRAM-controller overhead.

constexpr int T_STEPS = 100;

__global__ void __launch_bounds__(256) lif_kernel(
    const float4* __restrict__ in,
    float4* __restrict__ out,
    int n4)
{
    int i = blockIdx.x * blockDim.x + threadIdx.x;
    if (i >= n4) return;

    float4 mem = make_float4(0.f, 0.f, 0.f, 0.f);
    float4 syn = make_float4(0.f, 0.f, 0.f, 0.f);

    size_t idx = (size_t)i;
    const size_t stride = (size_t)n4;

    // Prologue: issue first load before entering the loop.
    float4 x = in[idx];

    #pragma unroll 5
    for (int t = 0; t < T_STEPS; ++t) {
        // Prefetch next input before this iteration's store.
        float4 x_next;
        if (t + 1 < T_STEPS)
            x_next = in[idx + stride];

        float4 o;
        o.x = (mem.x > 1.0f) ? 1.0f : 0.0f;
        o.y = (mem.y > 1.0f) ? 1.0f : 0.0f;
        o.z = (mem.z > 1.0f) ? 1.0f : 0.0f;
        o.w = (mem.w > 1.0f) ? 1.0f : 0.0f;

        out[idx] = o;

        mem.x = (0.5f * mem.x + syn.x) * (1.0f - o.x);
        mem.y = (0.5f * mem.y + syn.y) * (1.0f - o.y);
        mem.z = (0.5f * mem.z + syn.z) * (1.0f - o.z);
        mem.w = (0.5f * mem.w + syn.w) * (1.0f - o.w);

        syn = x;
        x = x_next;
        idx += stride;
    }
}

extern "C" void kernel_launch(void* const* d_in, const int* in_sizes, int n_in,
                              void* d_out, int out_size)
{
    const float* in = (const float*)d_in[0];
    float* out = (float*)d_out;

    const int BN = in_sizes[0] / T_STEPS;  // 524288
    const int n4 = BN / 4;                 // 131072 float4 lanes

    const int threads = 256;
    const int blocks = (n4 + threads - 1) / threads;  // 512

    lif_kernel<<<blocks, threads>>>(
        (const float4*)in, (float4*)out, n4);
}